// round 12
// baseline (speedup 1.0000x reference)
#include <cuda_runtime.h>
#include <cuda_bf16.h>
#include <math.h>

#define NN 2
#define CC 256
#define HH 96
#define WW 96
#define HS 48
#define PP 2304
#define COLS 4608
#define GG 8
#define DD 32
#define DPW 33

// ---------------- scratch ----------------
__device__ __align__(16) __nv_bfloat16 g_wA[3 * CC * CC];
__device__ __align__(16) __nv_bfloat16 g_wp[CC * CC];
__device__ __align__(16) __nv_bfloat16 g_xsT[COLS * CC];
__device__ __align__(16) float g_qkv[3 * CC * COLS];
__device__ __align__(16) float g_px[95 * CC];
__device__ __align__(16) float g_py[95 * CC];
__device__ __align__(16) float g_wxt[128 * CC];
__device__ __align__(16) float g_wyt[128 * CC];
__device__ __align__(16) float g_ex[16 * PP * 48];
__device__ __align__(16) float g_eyT[16 * 48 * PP];
__device__ __align__(16) float g_ek[16 * PP];
__device__ __align__(16) __nv_bfloat16 g_wt[16 * 48 * DPW * 48];
__device__ __align__(16) __nv_bfloat16 g_attT[COLS * CC];
__device__ __align__(16) float g_proj[CC * COLS];

// ---------------- helpers ----------------
__device__ __forceinline__ unsigned pack2(float2 f) {
    __nv_bfloat162 h = __float22bfloat162_rn(f);
    return *reinterpret_cast<unsigned*>(&h);
}
__device__ __forceinline__ unsigned hmul2u(unsigned a, __nv_bfloat162 b) {
    __nv_bfloat162 av = *reinterpret_cast<__nv_bfloat162*>(&a);
    __nv_bfloat162 r = __hmul2(av, b);
    return *reinterpret_cast<unsigned*>(&r);
}
__device__ __forceinline__ void mma16816(float d[4], const unsigned a[4], unsigned b0,
                                         unsigned b1) {
    asm volatile(
        "mma.sync.aligned.m16n8k16.row.col.f32.bf16.bf16.f32 "
        "{%0,%1,%2,%3}, {%4,%5,%6,%7}, {%8,%9}, {%0,%1,%2,%3};\n"
        : "+f"(d[0]), "+f"(d[1]), "+f"(d[2]), "+f"(d[3])
        : "r"(a[0]), "r"(a[1]), "r"(a[2]), "r"(a[3]), "r"(b0), "r"(b1));
}
__device__ __forceinline__ void cpa16(void* smem, const void* gmem) {
    unsigned saddr = (unsigned)__cvta_generic_to_shared(smem);
    asm volatile("cp.async.ca.shared.global [%0], [%1], 16;\n" ::"r"(saddr), "l"(gmem));
}
#define CPA_COMMIT asm volatile("cp.async.commit_group;\n" ::)
#define CPA_WAIT1 asm volatile("cp.async.wait_group 1;\n" ::)
#define CPA_WAIT0 asm volatile("cp.async.wait_group 0;\n" ::)

// ---------------- prep ----------------
__global__ void k_prep_w(const float* __restrict__ Wq, const float* __restrict__ Wk,
                         const float* __restrict__ Wv, const float* __restrict__ Wp,
                         const float* __restrict__ Wx, const float* __restrict__ Wy) {
    int b = blockIdx.x;
    int t = threadIdx.x;
    if (b < 256) {
        int i = b * 256 + t;
        g_wA[i] = __float2bfloat16(Wq[i]);
        g_wA[65536 + i] = __float2bfloat16(Wk[i]);
        g_wA[131072 + i] = __float2bfloat16(Wv[i]);
        g_wp[i] = __float2bfloat16(Wp[i]);
    } else {
        int f = b - 256;
        g_wxt[f * CC + t] = Wx[t * 128 + f];
        g_wyt[f * CC + t] = Wy[t * 128 + f];
    }
}

__global__ void __launch_bounds__(256) k_subT(const float* __restrict__ x) {
    __shared__ float tile[32][33];
    int col0 = blockIdx.x * 32, c0 = blockIdx.y * 32;
    int t = threadIdx.x, tx = t % 32, ty = t / 32;
#pragma unroll
    for (int j = 0; j < 4; j++) {
        int c = c0 + ty + j * 8;
        int col = col0 + tx;
        int n = col / PP, p = col % PP;
        int ph = p / HS, pw = p % HS;
        tile[ty + j * 8][tx] = x[((n * CC + c) * HH + ph * 2) * WW + pw * 2];
    }
    __syncthreads();
#pragma unroll
    for (int j = 0; j < 4; j++) {
        int col = col0 + ty + j * 8;
        int c = c0 + tx;
        g_xsT[(size_t)col * CC + c] = __float2bfloat16(tile[tx][ty + j * 8]);
    }
}

// ---------------- pos: grid (95, 8) ----------------
__global__ void __launch_bounds__(256) k_pos2() {
    __shared__ float bs[128];
    __shared__ float part[4][64];
    int dl = blockIdx.x;
    int y = blockIdx.y;
    int axis = y & 1;
    int quad = y >> 1;
    const float* w = axis ? g_wyt : g_wxt;
    float Dv = 2.0f * (float)(dl - 47);
    int t = threadIdx.x;
    if (t < 128) {
        int f = t & 63;
        float m = powf(1000.0f, (float)f * (1.0f / 64.0f));
        float a = Dv / m;
        bs[t] = (t < 64) ? sinf(a) : cosf(a);
    }
    __syncthreads();
    int chl = t & 63;
    int fg = t >> 6;
    int ch = quad * 64 + chl;
    float s = 0.f;
#pragma unroll
    for (int fo = 0; fo < 32; fo++) {
        int f = fg * 32 + fo;
        s += bs[f] * w[f * CC + ch];
    }
    part[fg][chl] = s;
    __syncthreads();
    if (t < 64) {
        float r = (part[0][t] + part[1][t]) + (part[2][t] + part[3][t]);
        float* dst = axis ? g_py : g_px;
        dst[dl * CC + quad * 64 + t] = r * 0.70710678118654752f;
    }
}

// ---------------- qkv GEMM: 256x128 tile, 512 thr ----------------
#define QKV_SMEM ((2 * 256 * 40 + 2 * 128 * 40) * 2)
__global__ void __launch_bounds__(512) k_gemm_qkv() {
    extern __shared__ __align__(16) __nv_bfloat16 qsm[];
    __nv_bfloat16* As = qsm;
    __nv_bfloat16* Bs = qsm + 2 * 256 * 40;
    int t = threadIdx.x, lane = t & 31, wid = t >> 5;
    int g = lane >> 2, tg = lane & 3;
    int wm = wid & 7, wn = wid >> 3;
    int m0 = blockIdx.y * 256, n0 = blockIdx.x * 128;
    float acc[2][8][4] = {};
#pragma unroll
    for (int jj = t; jj < 1536; jj += 512) {
        if (jj < 1024) {
            int row = jj >> 2, qv = jj & 3;
            cpa16(As + row * 40 + qv * 8, g_wA + (size_t)(m0 + row) * 256 + qv * 8);
        } else {
            int j2 = jj - 1024;
            int row = j2 >> 2, qv = j2 & 3;
            cpa16(Bs + row * 40 + qv * 8, g_xsT + (size_t)(n0 + row) * 256 + qv * 8);
        }
    }
    CPA_COMMIT;
    for (int it = 0; it < 8; it++) {
        int cur = it & 1, nxt = cur ^ 1;
        if (it < 7) {
            int kc = (it + 1) * 32;
#pragma unroll
            for (int jj = t; jj < 1536; jj += 512) {
                if (jj < 1024) {
                    int row = jj >> 2, qv = jj & 3;
                    cpa16(As + nxt * 10240 + row * 40 + qv * 8,
                          g_wA + (size_t)(m0 + row) * 256 + kc + qv * 8);
                } else {
                    int j2 = jj - 1024;
                    int row = j2 >> 2, qv = j2 & 3;
                    cpa16(Bs + nxt * 5120 + row * 40 + qv * 8,
                          g_xsT + (size_t)(n0 + row) * 256 + kc + qv * 8);
                }
            }
            CPA_COMMIT;
            CPA_WAIT1;
        } else {
            CPA_WAIT0;
        }
        __syncthreads();
#pragma unroll
        for (int k2 = 0; k2 < 2; k2++) {
            unsigned ah[2][4];
#pragma unroll
            for (int mt = 0; mt < 2; mt++) {
                int r = wm * 32 + mt * 16 + g;
                const unsigned* p0 = (const unsigned*)(As + cur * 10240 + r * 40);
                const unsigned* p1 = (const unsigned*)(As + cur * 10240 + (r + 8) * 40);
                ah[mt][0] = p0[k2 * 8 + tg];
                ah[mt][1] = p1[k2 * 8 + tg];
                ah[mt][2] = p0[k2 * 8 + 4 + tg];
                ah[mt][3] = p1[k2 * 8 + 4 + tg];
            }
#pragma unroll
            for (int nt = 0; nt < 8; nt++) {
                int nr = wn * 64 + nt * 8 + g;
                const unsigned* pbs = (const unsigned*)(Bs + cur * 5120 + nr * 40);
                unsigned b0 = pbs[k2 * 8 + tg], b1 = pbs[k2 * 8 + 4 + tg];
#pragma unroll
                for (int mt = 0; mt < 2; mt++) mma16816(acc[mt][nt], ah[mt], b0, b1);
            }
        }
        __syncthreads();
    }
#pragma unroll
    for (int mt = 0; mt < 2; mt++) {
        int r = m0 + wm * 32 + mt * 16 + g;
#pragma unroll
        for (int nt = 0; nt < 8; nt++) {
            int col = n0 + wn * 64 + nt * 8 + tg * 2;
            *(float2*)&g_qkv[(size_t)r * COLS + col] = make_float2(acc[mt][nt][0], acc[mt][nt][1]);
            *(float2*)&g_qkv[(size_t)(r + 8) * COLS + col] =
                make_float2(acc[mt][nt][2], acc[mt][nt][3]);
        }
    }
}

// ---------------- Wp GEMM: 128x128 tile, kc=32 ----------------
__global__ void __launch_bounds__(256) k_gemm_wp() {
    __shared__ __align__(16) __nv_bfloat16 As[2][128][40];
    __shared__ __align__(16) __nv_bfloat16 Bs[2][128][40];
    int t = threadIdx.x, lane = t & 31, wid = t >> 5;
    int g = lane >> 2, tg = lane & 3;
    int wm = wid & 3, wn = wid >> 2;
    int m0 = blockIdx.y * 128, n0 = blockIdx.x * 128;
    float acc[2][8][4] = {};
#pragma unroll
    for (int jj = t; jj < 512; jj += 256) {
        int row = jj >> 2, qv = jj & 3;
        cpa16(&As[0][row][qv * 8], g_wp + (size_t)(m0 + row) * 256 + qv * 8);
        cpa16(&Bs[0][row][qv * 8], g_attT + (size_t)(n0 + row) * 256 + qv * 8);
    }
    CPA_COMMIT;
    for (int it = 0; it < 8; it++) {
        int cur = it & 1, nxt = cur ^ 1;
        if (it < 7) {
            int kc = (it + 1) * 32;
#pragma unroll
            for (int jj = t; jj < 512; jj += 256) {
                int row = jj >> 2, qv = jj & 3;
                cpa16(&As[nxt][row][qv * 8], g_wp + (size_t)(m0 + row) * 256 + kc + qv * 8);
                cpa16(&Bs[nxt][row][qv * 8], g_attT + (size_t)(n0 + row) * 256 + kc + qv * 8);
            }
            CPA_COMMIT;
            CPA_WAIT1;
        } else {
            CPA_WAIT0;
        }
        __syncthreads();
#pragma unroll
        for (int k2 = 0; k2 < 2; k2++) {
            unsigned ah[2][4];
#pragma unroll
            for (int mt = 0; mt < 2; mt++) {
                int r = wm * 32 + mt * 16 + g;
                const unsigned* p0 = (const unsigned*)As[cur][r];
                const unsigned* p1 = (const unsigned*)As[cur][r + 8];
                ah[mt][0] = p0[k2 * 8 + tg];
                ah[mt][1] = p1[k2 * 8 + tg];
                ah[mt][2] = p0[k2 * 8 + 4 + tg];
                ah[mt][3] = p1[k2 * 8 + 4 + tg];
            }
#pragma unroll
            for (int nt = 0; nt < 8; nt++) {
                int nr = wn * 64 + nt * 8 + g;
                const unsigned* pbs = (const unsigned*)Bs[cur][nr];
                unsigned b0 = pbs[k2 * 8 + tg], b1 = pbs[k2 * 8 + 4 + tg];
#pragma unroll
                for (int mt = 0; mt < 2; mt++) mma16816(acc[mt][nt], ah[mt], b0, b1);
            }
        }
        __syncthreads();
    }
#pragma unroll
    for (int mt = 0; mt < 2; mt++) {
        int r = m0 + wm * 32 + mt * 16 + g;
#pragma unroll
        for (int nt = 0; nt < 8; nt++) {
            int col = n0 + wn * 64 + nt * 8 + tg * 2;
            *(float2*)&g_proj[(size_t)r * COLS + col] = make_float2(acc[mt][nt][0], acc[mt][nt][1]);
            *(float2*)&g_proj[(size_t)(r + 8) * COLS + col] =
                make_float2(acc[mt][nt][2], acc[mt][nt][3]);
        }
    }
}

// ---------------- ex/ey ----------------
__global__ void __launch_bounds__(256) k_exy() {
    int b = blockIdx.x;
    int h = b % HS;
    int ng = b / HS;
    int g = ng % GG, n = ng / GG;
    __shared__ float qs[48][33];
    __shared__ float pxs[95][33];
    __shared__ float pys[48][33];
    __shared__ float exm[48][49];
    __shared__ float eym[48][49];
    __shared__ float rmx[48], rmy[48];
    int t = threadIdx.x;
    for (int i = t; i < 48 * 32; i += 256) {
        int d = i / 48, w_ = i % 48;
        qs[w_][d] = g_qkv[(size_t)(g * DD + d) * COLS + n * PP + h * HS + w_];
    }
    for (int i = t; i < 95 * 32; i += 256) {
        int dl = i / 32, d = i % 32;
        pxs[dl][d] = g_px[dl * CC + g * DD + d];
    }
    for (int i = t; i < 48 * 32; i += 256) {
        int u = i / 32, d = i % 32;
        pys[u][d] = g_py[(h - u + 47) * CC + g * DD + d];
    }
    __syncthreads();
    for (int i = t; i < PP; i += 256) {
        int w_ = i / 48, v = i % 48;
        float s = 0.f, s2 = 0.f;
#pragma unroll
        for (int d = 0; d < 32; d++) {
            float qv = qs[w_][d];
            s += qv * pxs[w_ - v + 47][d];
            s2 += qv * pys[v][d];
        }
        exm[w_][v] = s;
        eym[w_][v] = s2;
    }
    __syncthreads();
    if (t < 48) {
        float m = -1e30f;
        for (int v = 0; v < 48; v++) m = fmaxf(m, exm[t][v]);
        rmx[t] = m;
    } else if (t < 96) {
        int w_ = t - 48;
        float m = -1e30f;
        for (int u = 0; u < 48; u++) m = fmaxf(m, eym[w_][u]);
        rmy[w_] = m;
    }
    __syncthreads();
    for (int i = t; i < PP; i += 256) {
        int w_ = i / 48, v = i % 48;
        g_ex[((size_t)ng * PP + h * HS + w_) * 48 + v] = expf(exm[w_][v] - rmx[w_]);
    }
    for (int i = t; i < PP; i += 256) {
        int u = i / 48, w_ = i % 48;
        g_eyT[((size_t)ng * 48 + u) * PP + h * HS + w_] = expf(eym[w_][u] - rmy[w_]);
    }
}

// ---------------- ek fused: dot + max + exp ----------------
__global__ void __launch_bounds__(256) k_ekf(const float* __restrict__ ab) {
    __shared__ float red[256];
    int ng = blockIdx.x;
    int g = ng % GG, n = ng / GG;
    int t = threadIdx.x;
    float ekv[9];
    float m = -1e30f;
#pragma unroll
    for (int j = 0; j < 9; j++) {
        int uv = j * 256 + t;
        float s = 0.f;
#pragma unroll
        for (int d = 0; d < 32; d++)
            s += ab[g * DD + d] * g_qkv[(size_t)(CC + g * DD + d) * COLS + n * PP + uv];
        ekv[j] = s;
        m = fmaxf(m, s);
    }
    red[t] = m;
    __syncthreads();
    for (int s = 128; s > 0; s >>= 1) {
        if (t < s) red[t] = fmaxf(red[t], red[t + s]);
        __syncthreads();
    }
    float mk = red[0];
#pragma unroll
    for (int j = 0; j < 9; j++) g_ek[(size_t)ng * PP + j * 256 + t] = expf(ekv[j] - mk);
}

// ---------------- Wt: one block per (ng,u), ek cached in smem ----------------
__global__ void __launch_bounds__(256) k_wt8() {
    __shared__ float eks[48];
    int b = blockIdx.x;  // 16*48
    int u = b % 48, ng = b / 48;
    int g = ng % GG, n = ng / GG;
    int t = threadIdx.x;
    if (t < 12)
        *(float4*)&eks[t * 4] = *(const float4*)&g_ek[(size_t)ng * PP + u * 48 + t * 4];
    __syncthreads();
    if (t >= 198) return;  // 33 rows * 6 threads/row
    int i = t * 8;
    int v = i % 48, d = i / 48;
    float e0 = eks[v], e1 = eks[v + 1], e2 = eks[v + 2], e3 = eks[v + 3];
    float e4 = eks[v + 4], e5 = eks[v + 5], e6 = eks[v + 6], e7 = eks[v + 7];
    unsigned r[4];
    if (d < 32) {
        size_t vo = (size_t)(2 * CC + g * DD + d) * COLS + n * PP + u * 48 + v;
        float4 v0 = *(const float4*)&g_qkv[vo];
        float4 v1 = *(const float4*)&g_qkv[vo + 4];
        r[0] = pack2(make_float2(e0 * v0.x, e1 * v0.y));
        r[1] = pack2(make_float2(e2 * v0.z, e3 * v0.w));
        r[2] = pack2(make_float2(e4 * v1.x, e5 * v1.y));
        r[3] = pack2(make_float2(e6 * v1.z, e7 * v1.w));
    } else {
        r[0] = pack2(make_float2(e0, e1));
        r[1] = pack2(make_float2(e2, e3));
        r[2] = pack2(make_float2(e4, e5));
        r[3] = pack2(make_float2(e6, e7));
    }
    *(uint4*)&g_wt[((size_t)ng * 48 + u) * DPW * 48 + i] = *(uint4*)r;
}

// ---------------- attention + Z fused in MMA, 512 thr, 8-u stages ---------------
#define WT_BUF (8 * 40 * 56)
#define ATT_SMEM (24576 + 2 * WT_BUF * 2)
__global__ void __launch_bounds__(512) k_attn_mma() {
    extern __shared__ __align__(16) char sm[];
    __nv_bfloat16* Eys = (__nv_bfloat16*)sm;
    __nv_bfloat16* Wth = (__nv_bfloat16*)(sm + 24576);
    int ng = blockIdx.y;
    int q0 = blockIdx.x * 256;
    int t = threadIdx.x, lane = t & 31, wid = t >> 5;
    int g = lane >> 2, tg = lane & 3;
    const __nv_bfloat16* wt_g = g_wt + (size_t)ng * 48 * DPW * 48;
    {
        unsigned* wz = (unsigned*)Wth;
        for (int j = t; j < 3136; j += 512) {
            int cc = j % 28;
            int row = j / 28;
            int uu = row % 8;
            int dd = 33 + (row / 8) % 7;
            int bb = row / 56;
            wz[bb * (WT_BUF / 2) + (uu * 40 + dd) * 28 + cc] = 0u;
        }
    }
    for (int j = t; j < 1584; j += 512) {
        int vq = j % 6, dd = (j / 6) % 33, uu = j / 198;
        cpa16(&Wth[(uu * 40 + dd) * 56 + vq * 8],
              wt_g + ((size_t)uu * DPW + dd) * 48 + vq * 8);
    }
    CPA_COMMIT;
    for (int i = t; i < 48 * 128; i += 512) {
        int u = i >> 7, qp = i & 127;
        float2 v2 = *(const float2*)&g_eyT[((size_t)ng * 48 + u) * PP + q0 + qp * 2];
        *(unsigned*)&Eys[u * 256 + qp * 2] = pack2(v2);
    }
    int qw = q0 + wid * 16;
    int qr0 = qw + g, qr1 = qr0 + 8;
    const float* exb = g_ex + (size_t)ng * PP * 48;
    unsigned exh[3][4];
#pragma unroll
    for (int ks = 0; ks < 3; ks++) {
        int v0 = ks * 16 + tg * 2;
        exh[ks][0] = pack2(*(const float2*)&exb[(size_t)qr0 * 48 + v0]);
        exh[ks][1] = pack2(*(const float2*)&exb[(size_t)qr1 * 48 + v0]);
        exh[ks][2] = pack2(*(const float2*)&exb[(size_t)qr0 * 48 + v0 + 8]);
        exh[ks][3] = pack2(*(const float2*)&exb[(size_t)qr1 * 48 + v0 + 8]);
    }
    float acc[5][4] = {};
    for (int it = 0; it < 6; it++) {
        int cur = it & 1, nxt = cur ^ 1;
        if (it < 5) {
            int uc = (it + 1) * 8;
            for (int j = t; j < 1584; j += 512) {
                int vq = j % 6, dd = (j / 6) % 33, uu = j / 198;
                cpa16(&Wth[nxt * WT_BUF + (uu * 40 + dd) * 56 + vq * 8],
                      wt_g + ((size_t)(uc + uu) * DPW + dd) * 48 + vq * 8);
            }
            CPA_COMMIT;
            CPA_WAIT1;
        } else {
            CPA_WAIT0;
        }
        __syncthreads();
#pragma unroll
        for (int uu = 0; uu < 8; uu++) {
            int u = it * 8 + uu;
            __nv_bfloat162 e0 = __bfloat162bfloat162(Eys[u * 256 + wid * 16 + g]);
            __nv_bfloat162 e1 = __bfloat162bfloat162(Eys[u * 256 + wid * 16 + g + 8]);
            unsigned sa[3][4];
#pragma unroll
            for (int ks = 0; ks < 3; ks++) {
                sa[ks][0] = hmul2u(exh[ks][0], e0);
                sa[ks][1] = hmul2u(exh[ks][1], e1);
                sa[ks][2] = hmul2u(exh[ks][2], e0);
                sa[ks][3] = hmul2u(exh[ks][3], e1);
            }
            const unsigned* pbh = (const unsigned*)(Wth + cur * WT_BUF + uu * 40 * 56);
#pragma unroll
            for (int nt = 0; nt < 5; nt++) {
#pragma unroll
                for (int ks = 0; ks < 3; ks++) {
                    int widx = (nt * 8 + g) * 28 + ks * 8 + tg;
                    mma16816(acc[nt], sa[ks], pbh[widx], pbh[widx + 4]);
                }
            }
        }
        __syncthreads();
    }
    int n = ng >> 3, gh = ng & 7;
    int src = (lane >> 2) << 2;
    float z0 = __shfl_sync(0xffffffffu, acc[4][0], src);
    float z1 = __shfl_sync(0xffffffffu, acc[4][2], src);
    float zi0 = 1.0f / z0, zi1 = 1.0f / z1;
    size_t col0 = (size_t)(n * PP + qr0) * CC;
    size_t col1 = (size_t)(n * PP + qr1) * CC;
#pragma unroll
    for (int nt = 0; nt < 4; nt++) {
        int c = gh * DD + nt * 8 + tg * 2;
        __nv_bfloat162 b0 =
            __float22bfloat162_rn(make_float2(acc[nt][0] * zi0, acc[nt][1] * zi0));
        __nv_bfloat162 b1 =
            __float22bfloat162_rn(make_float2(acc[nt][2] * zi1, acc[nt][3] * zi1));
        *(__nv_bfloat162*)&g_attT[col0 + c] = b0;
        *(__nv_bfloat162*)&g_attT[col1 + c] = b1;
    }
}

// ---------------- bilinear upsample + bias + residual ----------------
__device__ __forceinline__ void taps48(int o, int& i0, int& i1, float& w0, float& w1) {
    int tt = o >> 1;
    if ((o & 1) == 0) {
        if (tt == 0) { i0 = 0; i1 = 0; w0 = 1.f; w1 = 0.f; }
        else { i0 = tt - 1; i1 = tt; w0 = 0.25f; w1 = 0.75f; }
    } else {
        if (tt == 47) { i0 = 47; i1 = 47; w0 = 1.f; w1 = 0.f; }
        else { i0 = tt; i1 = tt + 1; w0 = 0.75f; w1 = 0.25f; }
    }
}

__global__ void k_final(const float* __restrict__ x, const float* __restrict__ bp,
                        const float* __restrict__ gamma, float* __restrict__ out) {
    int i = blockIdx.x * 256 + threadIdx.x;
    int j = i % WW;
    int r = (i / WW) % HH;
    int c = (i / (HH * WW)) % CC;
    int n = i / (CC * HH * WW);
    int r0, r1, c0, c1;
    float rw0, rw1, cw0, cw1;
    taps48(r, r0, r1, rw0, rw1);
    taps48(j, c0, c1, cw0, cw1);
    const float* pr = g_proj + (size_t)c * COLS + n * PP;
    float v00 = pr[r0 * HS + c0], v01 = pr[r0 * HS + c1];
    float v10 = pr[r1 * HS + c0], v11 = pr[r1 * HS + c1];
    float bi = rw0 * (cw0 * v00 + cw1 * v01) + rw1 * (cw0 * v10 + cw1 * v11);
    out[i] = gamma[0] * (bi + bp[c]) + x[i];
}

// ---------------- launch ----------------
extern "C" void kernel_launch(void* const* d_in, const int* in_sizes, int n_in,
                              void* d_out, int out_size) {
    (void)in_sizes; (void)n_in; (void)out_size;
    const float* x = (const float*)d_in[0];
    const float* Wq = (const float*)d_in[1];
    const float* Wk = (const float*)d_in[2];
    const float* Wv = (const float*)d_in[3];
    const float* Wx = (const float*)d_in[4];
    const float* Wy = (const float*)d_in[5];
    const float* ab = (const float*)d_in[6];
    const float* Wp = (const float*)d_in[7];
    const float* bp = (const float*)d_in[8];
    const float* gamma = (const float*)d_in[9];
    float* out = (float*)d_out;

    cudaFuncSetAttribute(k_attn_mma, cudaFuncAttributeMaxDynamicSharedMemorySize,
                         ATT_SMEM);
    cudaFuncSetAttribute(k_gemm_qkv, cudaFuncAttributeMaxDynamicSharedMemorySize,
                         QKV_SMEM);

    k_prep_w<<<384, 256>>>(Wq, Wk, Wv, Wp, Wx, Wy);
    k_subT<<<dim3(COLS / 32, CC / 32), 256>>>(x);
    k_pos2<<<dim3(95, 8), 256>>>();
    k_gemm_qkv<<<dim3(36, 3), 512, QKV_SMEM>>>();
    k_exy<<<16 * HS, 256>>>();
    k_ekf<<<16, 256>>>(ab);
    k_wt8<<<16 * 48, 256>>>();
    k_attn_mma<<<dim3(PP / 256, 16), 512, ATT_SMEM>>>();
    k_gemm_wp<<<dim3(36, 2), 256>>>();
    k_final<<<(NN * CC * HH * WW) / 256, 256>>>(x, bp, gamma, out);
}

// round 13
// speedup vs baseline: 1.0187x; 1.0187x over previous
#include <cuda_runtime.h>
#include <cuda_bf16.h>
#include <math.h>

#define NN 2
#define CC 256
#define HH 96
#define WW 96
#define HS 48
#define PP 2304
#define COLS 4608
#define GG 8
#define DD 32
#define DPW 33

// ---------------- scratch ----------------
__device__ __align__(16) __nv_bfloat16 g_wA[3 * CC * CC];
__device__ __align__(16) __nv_bfloat16 g_wp[CC * CC];
__device__ __align__(16) __nv_bfloat16 g_xsT[COLS * CC];
__device__ __align__(16) float g_qkv[3 * CC * COLS];
__device__ __align__(16) float g_px[95 * CC];
__device__ __align__(16) float g_py[95 * CC];
__device__ __align__(16) float g_wxt[128 * CC];
__device__ __align__(16) float g_wyt[128 * CC];
__device__ __align__(16) float g_ex[16 * PP * 48];
__device__ __align__(16) float g_eyT[16 * 48 * PP];
__device__ __align__(16) float g_ek[16 * PP];
__device__ __align__(16) __nv_bfloat16 g_wt[16 * 48 * DPW * 48];
__device__ __align__(16) __nv_bfloat16 g_attT[COLS * CC];
__device__ __align__(16) float g_proj[CC * COLS];

// ---------------- helpers ----------------
__device__ __forceinline__ unsigned pack2(float2 f) {
    __nv_bfloat162 h = __float22bfloat162_rn(f);
    return *reinterpret_cast<unsigned*>(&h);
}
__device__ __forceinline__ unsigned hmul2u(unsigned a, __nv_bfloat162 b) {
    __nv_bfloat162 av = *reinterpret_cast<__nv_bfloat162*>(&a);
    __nv_bfloat162 r = __hmul2(av, b);
    return *reinterpret_cast<unsigned*>(&r);
}
__device__ __forceinline__ void mma16816(float d[4], const unsigned a[4], unsigned b0,
                                         unsigned b1) {
    asm volatile(
        "mma.sync.aligned.m16n8k16.row.col.f32.bf16.bf16.f32 "
        "{%0,%1,%2,%3}, {%4,%5,%6,%7}, {%8,%9}, {%0,%1,%2,%3};\n"
        : "+f"(d[0]), "+f"(d[1]), "+f"(d[2]), "+f"(d[3])
        : "r"(a[0]), "r"(a[1]), "r"(a[2]), "r"(a[3]), "r"(b0), "r"(b1));
}
__device__ __forceinline__ void cpa16(void* smem, const void* gmem) {
    unsigned saddr = (unsigned)__cvta_generic_to_shared(smem);
    asm volatile("cp.async.ca.shared.global [%0], [%1], 16;\n" ::"r"(saddr), "l"(gmem));
}
#define CPA_COMMIT asm volatile("cp.async.commit_group;\n" ::)
#define CPA_WAIT1 asm volatile("cp.async.wait_group 1;\n" ::)
#define CPA_WAIT0 asm volatile("cp.async.wait_group 0;\n" ::)

// ---------------- prep ----------------
__global__ void k_prep_w(const float* __restrict__ Wq, const float* __restrict__ Wk,
                         const float* __restrict__ Wv, const float* __restrict__ Wp,
                         const float* __restrict__ Wx, const float* __restrict__ Wy) {
    int b = blockIdx.x;
    int t = threadIdx.x;
    if (b < 256) {
        int i = b * 256 + t;
        g_wA[i] = __float2bfloat16(Wq[i]);
        g_wA[65536 + i] = __float2bfloat16(Wk[i]);
        g_wA[131072 + i] = __float2bfloat16(Wv[i]);
        g_wp[i] = __float2bfloat16(Wp[i]);
    } else {
        int f = b - 256;
        g_wxt[f * CC + t] = Wx[t * 128 + f];
        g_wyt[f * CC + t] = Wy[t * 128 + f];
    }
}

__global__ void __launch_bounds__(256) k_subT(const float* __restrict__ x) {
    __shared__ float tile[32][33];
    int col0 = blockIdx.x * 32, c0 = blockIdx.y * 32;
    int t = threadIdx.x, tx = t % 32, ty = t / 32;
#pragma unroll
    for (int j = 0; j < 4; j++) {
        int c = c0 + ty + j * 8;
        int col = col0 + tx;
        int n = col / PP, p = col % PP;
        int ph = p / HS, pw = p % HS;
        tile[ty + j * 8][tx] = x[((n * CC + c) * HH + ph * 2) * WW + pw * 2];
    }
    __syncthreads();
#pragma unroll
    for (int j = 0; j < 4; j++) {
        int col = col0 + ty + j * 8;
        int c = c0 + tx;
        g_xsT[(size_t)col * CC + c] = __float2bfloat16(tile[tx][ty + j * 8]);
    }
}

// ---------------- pos: grid (95, 8) ----------------
__global__ void __launch_bounds__(256) k_pos2() {
    __shared__ float bs[128];
    __shared__ float part[4][64];
    int dl = blockIdx.x;
    int y = blockIdx.y;
    int axis = y & 1;
    int quad = y >> 1;
    const float* w = axis ? g_wyt : g_wxt;
    float Dv = 2.0f * (float)(dl - 47);
    int t = threadIdx.x;
    if (t < 128) {
        int f = t & 63;
        float m = powf(1000.0f, (float)f * (1.0f / 64.0f));
        float a = Dv / m;
        bs[t] = (t < 64) ? sinf(a) : cosf(a);
    }
    __syncthreads();
    int chl = t & 63;
    int fg = t >> 6;
    int ch = quad * 64 + chl;
    float s = 0.f;
#pragma unroll
    for (int fo = 0; fo < 32; fo++) {
        int f = fg * 32 + fo;
        s += bs[f] * w[f * CC + ch];
    }
    part[fg][chl] = s;
    __syncthreads();
    if (t < 64) {
        float r = (part[0][t] + part[1][t]) + (part[2][t] + part[3][t]);
        float* dst = axis ? g_py : g_px;
        dst[dl * CC + quad * 64 + t] = r * 0.70710678118654752f;
    }
}

// ---------------- qkv GEMM: 256x128 tile, 512 thr ----------------
#define QKV_SMEM ((2 * 256 * 40 + 2 * 128 * 40) * 2)
__global__ void __launch_bounds__(512) k_gemm_qkv() {
    extern __shared__ __align__(16) __nv_bfloat16 qsm[];
    __nv_bfloat16* As = qsm;
    __nv_bfloat16* Bs = qsm + 2 * 256 * 40;
    int t = threadIdx.x, lane = t & 31, wid = t >> 5;
    int g = lane >> 2, tg = lane & 3;
    int wm = wid & 7, wn = wid >> 3;
    int m0 = blockIdx.y * 256, n0 = blockIdx.x * 128;
    float acc[2][8][4] = {};
#pragma unroll
    for (int jj = t; jj < 1536; jj += 512) {
        if (jj < 1024) {
            int row = jj >> 2, qv = jj & 3;
            cpa16(As + row * 40 + qv * 8, g_wA + (size_t)(m0 + row) * 256 + qv * 8);
        } else {
            int j2 = jj - 1024;
            int row = j2 >> 2, qv = j2 & 3;
            cpa16(Bs + row * 40 + qv * 8, g_xsT + (size_t)(n0 + row) * 256 + qv * 8);
        }
    }
    CPA_COMMIT;
    for (int it = 0; it < 8; it++) {
        int cur = it & 1, nxt = cur ^ 1;
        if (it < 7) {
            int kc = (it + 1) * 32;
#pragma unroll
            for (int jj = t; jj < 1536; jj += 512) {
                if (jj < 1024) {
                    int row = jj >> 2, qv = jj & 3;
                    cpa16(As + nxt * 10240 + row * 40 + qv * 8,
                          g_wA + (size_t)(m0 + row) * 256 + kc + qv * 8);
                } else {
                    int j2 = jj - 1024;
                    int row = j2 >> 2, qv = j2 & 3;
                    cpa16(Bs + nxt * 5120 + row * 40 + qv * 8,
                          g_xsT + (size_t)(n0 + row) * 256 + kc + qv * 8);
                }
            }
            CPA_COMMIT;
            CPA_WAIT1;
        } else {
            CPA_WAIT0;
        }
        __syncthreads();
#pragma unroll
        for (int k2 = 0; k2 < 2; k2++) {
            unsigned ah[2][4];
#pragma unroll
            for (int mt = 0; mt < 2; mt++) {
                int r = wm * 32 + mt * 16 + g;
                const unsigned* p0 = (const unsigned*)(As + cur * 10240 + r * 40);
                const unsigned* p1 = (const unsigned*)(As + cur * 10240 + (r + 8) * 40);
                ah[mt][0] = p0[k2 * 8 + tg];
                ah[mt][1] = p1[k2 * 8 + tg];
                ah[mt][2] = p0[k2 * 8 + 4 + tg];
                ah[mt][3] = p1[k2 * 8 + 4 + tg];
            }
#pragma unroll
            for (int nt = 0; nt < 8; nt++) {
                int nr = wn * 64 + nt * 8 + g;
                const unsigned* pbs = (const unsigned*)(Bs + cur * 5120 + nr * 40);
                unsigned b0 = pbs[k2 * 8 + tg], b1 = pbs[k2 * 8 + 4 + tg];
#pragma unroll
                for (int mt = 0; mt < 2; mt++) mma16816(acc[mt][nt], ah[mt], b0, b1);
            }
        }
        __syncthreads();
    }
#pragma unroll
    for (int mt = 0; mt < 2; mt++) {
        int r = m0 + wm * 32 + mt * 16 + g;
#pragma unroll
        for (int nt = 0; nt < 8; nt++) {
            int col = n0 + wn * 64 + nt * 8 + tg * 2;
            *(float2*)&g_qkv[(size_t)r * COLS + col] = make_float2(acc[mt][nt][0], acc[mt][nt][1]);
            *(float2*)&g_qkv[(size_t)(r + 8) * COLS + col] =
                make_float2(acc[mt][nt][2], acc[mt][nt][3]);
        }
    }
}

// ---------------- Wp GEMM: 128x128 tile, kc=32 ----------------
__global__ void __launch_bounds__(256) k_gemm_wp() {
    __shared__ __align__(16) __nv_bfloat16 As[2][128][40];
    __shared__ __align__(16) __nv_bfloat16 Bs[2][128][40];
    int t = threadIdx.x, lane = t & 31, wid = t >> 5;
    int g = lane >> 2, tg = lane & 3;
    int wm = wid & 3, wn = wid >> 2;
    int m0 = blockIdx.y * 128, n0 = blockIdx.x * 128;
    float acc[2][8][4] = {};
#pragma unroll
    for (int jj = t; jj < 512; jj += 256) {
        int row = jj >> 2, qv = jj & 3;
        cpa16(&As[0][row][qv * 8], g_wp + (size_t)(m0 + row) * 256 + qv * 8);
        cpa16(&Bs[0][row][qv * 8], g_attT + (size_t)(n0 + row) * 256 + qv * 8);
    }
    CPA_COMMIT;
    for (int it = 0; it < 8; it++) {
        int cur = it & 1, nxt = cur ^ 1;
        if (it < 7) {
            int kc = (it + 1) * 32;
#pragma unroll
            for (int jj = t; jj < 512; jj += 256) {
                int row = jj >> 2, qv = jj & 3;
                cpa16(&As[nxt][row][qv * 8], g_wp + (size_t)(m0 + row) * 256 + kc + qv * 8);
                cpa16(&Bs[nxt][row][qv * 8], g_attT + (size_t)(n0 + row) * 256 + kc + qv * 8);
            }
            CPA_COMMIT;
            CPA_WAIT1;
        } else {
            CPA_WAIT0;
        }
        __syncthreads();
#pragma unroll
        for (int k2 = 0; k2 < 2; k2++) {
            unsigned ah[2][4];
#pragma unroll
            for (int mt = 0; mt < 2; mt++) {
                int r = wm * 32 + mt * 16 + g;
                const unsigned* p0 = (const unsigned*)As[cur][r];
                const unsigned* p1 = (const unsigned*)As[cur][r + 8];
                ah[mt][0] = p0[k2 * 8 + tg];
                ah[mt][1] = p1[k2 * 8 + tg];
                ah[mt][2] = p0[k2 * 8 + 4 + tg];
                ah[mt][3] = p1[k2 * 8 + 4 + tg];
            }
#pragma unroll
            for (int nt = 0; nt < 8; nt++) {
                int nr = wn * 64 + nt * 8 + g;
                const unsigned* pbs = (const unsigned*)Bs[cur][nr];
                unsigned b0 = pbs[k2 * 8 + tg], b1 = pbs[k2 * 8 + 4 + tg];
#pragma unroll
                for (int mt = 0; mt < 2; mt++) mma16816(acc[mt][nt], ah[mt], b0, b1);
            }
        }
        __syncthreads();
    }
#pragma unroll
    for (int mt = 0; mt < 2; mt++) {
        int r = m0 + wm * 32 + mt * 16 + g;
#pragma unroll
        for (int nt = 0; nt < 8; nt++) {
            int col = n0 + wn * 64 + nt * 8 + tg * 2;
            *(float2*)&g_proj[(size_t)r * COLS + col] = make_float2(acc[mt][nt][0], acc[mt][nt][1]);
            *(float2*)&g_proj[(size_t)(r + 8) * COLS + col] =
                make_float2(acc[mt][nt][2], acc[mt][nt][3]);
        }
    }
}

// ---------------- ex/ey ----------------
__global__ void __launch_bounds__(256) k_exy() {
    int b = blockIdx.x;
    int h = b % HS;
    int ng = b / HS;
    int g = ng % GG, n = ng / GG;
    __shared__ float qs[48][33];
    __shared__ float pxs[95][33];
    __shared__ float pys[48][33];
    __shared__ float exm[48][49];
    __shared__ float eym[48][49];
    __shared__ float rmx[48], rmy[48];
    int t = threadIdx.x;
    for (int i = t; i < 48 * 32; i += 256) {
        int d = i / 48, w_ = i % 48;
        qs[w_][d] = g_qkv[(size_t)(g * DD + d) * COLS + n * PP + h * HS + w_];
    }
    for (int i = t; i < 95 * 32; i += 256) {
        int dl = i / 32, d = i % 32;
        pxs[dl][d] = g_px[dl * CC + g * DD + d];
    }
    for (int i = t; i < 48 * 32; i += 256) {
        int u = i / 32, d = i % 32;
        pys[u][d] = g_py[(h - u + 47) * CC + g * DD + d];
    }
    __syncthreads();
    for (int i = t; i < PP; i += 256) {
        int w_ = i / 48, v = i % 48;
        float s = 0.f, s2 = 0.f;
#pragma unroll
        for (int d = 0; d < 32; d++) {
            float qv = qs[w_][d];
            s += qv * pxs[w_ - v + 47][d];
            s2 += qv * pys[v][d];
        }
        exm[w_][v] = s;
        eym[w_][v] = s2;
    }
    __syncthreads();
    if (t < 48) {
        float m = -1e30f;
        for (int v = 0; v < 48; v++) m = fmaxf(m, exm[t][v]);
        rmx[t] = m;
    } else if (t < 96) {
        int w_ = t - 48;
        float m = -1e30f;
        for (int u = 0; u < 48; u++) m = fmaxf(m, eym[w_][u]);
        rmy[w_] = m;
    }
    __syncthreads();
    for (int i = t; i < PP; i += 256) {
        int w_ = i / 48, v = i % 48;
        g_ex[((size_t)ng * PP + h * HS + w_) * 48 + v] = expf(exm[w_][v] - rmx[w_]);
    }
    for (int i = t; i < PP; i += 256) {
        int u = i / 48, w_ = i % 48;
        g_eyT[((size_t)ng * 48 + u) * PP + h * HS + w_] = expf(eym[w_][u] - rmy[w_]);
    }
}

// ---------------- ek fused: dot + max + exp ----------------
__global__ void __launch_bounds__(256) k_ekf(const float* __restrict__ ab) {
    __shared__ float red[256];
    int ng = blockIdx.x;
    int g = ng % GG, n = ng / GG;
    int t = threadIdx.x;
    float ekv[9];
    float m = -1e30f;
#pragma unroll
    for (int j = 0; j < 9; j++) {
        int uv = j * 256 + t;
        float s = 0.f;
#pragma unroll
        for (int d = 0; d < 32; d++)
            s += ab[g * DD + d] * g_qkv[(size_t)(CC + g * DD + d) * COLS + n * PP + uv];
        ekv[j] = s;
        m = fmaxf(m, s);
    }
    red[t] = m;
    __syncthreads();
    for (int s = 128; s > 0; s >>= 1) {
        if (t < s) red[t] = fmaxf(red[t], red[t + s]);
        __syncthreads();
    }
    float mk = red[0];
#pragma unroll
    for (int j = 0; j < 9; j++) g_ek[(size_t)ng * PP + j * 256 + t] = expf(ekv[j] - mk);
}

// ---------------- Wt bf16 [ng][u][33][48], flat 8/thread ----------------
__global__ void k_wt8() {
    int i = (blockIdx.x * 256 + threadIdx.x) * 8;
    int v = i % 48;
    int d = (i / 48) % DPW;
    int u = (i / (48 * DPW)) % 48;
    int ng = i / (48 * DPW * 48);
    int g = ng % GG, n = ng / GG;
    size_t eko = (size_t)ng * PP + u * 48 + v;
    float4 e0 = *(const float4*)&g_ek[eko];
    float4 e1 = *(const float4*)&g_ek[eko + 4];
    unsigned r[4];
    if (d < 32) {
        size_t vo = (size_t)(2 * CC + g * DD + d) * COLS + n * PP + u * 48 + v;
        float4 v0 = *(const float4*)&g_qkv[vo];
        float4 v1 = *(const float4*)&g_qkv[vo + 4];
        r[0] = pack2(make_float2(e0.x * v0.x, e0.y * v0.y));
        r[1] = pack2(make_float2(e0.z * v0.z, e0.w * v0.w));
        r[2] = pack2(make_float2(e1.x * v1.x, e1.y * v1.y));
        r[3] = pack2(make_float2(e1.z * v1.z, e1.w * v1.w));
    } else {
        r[0] = pack2(make_float2(e0.x, e0.y));
        r[1] = pack2(make_float2(e0.z, e0.w));
        r[2] = pack2(make_float2(e1.x, e1.y));
        r[3] = pack2(make_float2(e1.z, e1.w));
    }
    *(uint4*)&g_wt[i] = *(uint4*)r;
}

// ---------------- attention + Z fused in MMA, 256 thr, 2 m-tiles/warp, LDSM -----
#define WT_BUF (8 * 40 * 56)
#define ATT_SMEM (24576 + 2 * WT_BUF * 2)
__global__ void __launch_bounds__(256) k_attn_mma() {
    extern __shared__ __align__(16) char sm[];
    __nv_bfloat16* Eys = (__nv_bfloat16*)sm;
    __nv_bfloat16* Wth = (__nv_bfloat16*)(sm + 24576);
    int ng = blockIdx.y;
    int q0 = blockIdx.x * 256;
    int t = threadIdx.x, lane = t & 31, wid = t >> 5;
    int g = lane >> 2, tg = lane & 3;
    const __nv_bfloat16* wt_g = g_wt + (size_t)ng * 48 * DPW * 48;
    // zero pad rows d=33..39 (stay zero)
    {
        unsigned* wz = (unsigned*)Wth;
        for (int j = t; j < 3136; j += 256) {
            int cc = j % 28;
            int row = j / 28;
            int uu = row % 8;
            int dd = 33 + (row / 8) % 7;
            int bb = row / 56;
            wz[bb * (WT_BUF / 2) + (uu * 40 + dd) * 28 + cc] = 0u;
        }
    }
    for (int j = t; j < 1584; j += 256) {
        int vq = j % 6, dd = (j / 6) % 33, uu = j / 198;
        cpa16(&Wth[(uu * 40 + dd) * 56 + vq * 8],
              wt_g + ((size_t)uu * DPW + dd) * 48 + vq * 8);
    }
    CPA_COMMIT;
    for (int i = t; i < 48 * 128; i += 256) {
        int u = i >> 7, qp = i & 127;
        float2 v2 = *(const float2*)&g_eyT[((size_t)ng * 48 + u) * PP + q0 + qp * 2];
        *(unsigned*)&Eys[u * 256 + qp * 2] = pack2(v2);
    }
    // Ex fragments, 2 m-tiles per warp
    int qw = q0 + wid * 32;
    const float* exb = g_ex + (size_t)ng * PP * 48;
    unsigned exh[2][3][4];
#pragma unroll
    for (int mt = 0; mt < 2; mt++) {
        int qr0 = qw + mt * 16 + g, qr1 = qr0 + 8;
#pragma unroll
        for (int ks = 0; ks < 3; ks++) {
            int v0 = ks * 16 + tg * 2;
            exh[mt][ks][0] = pack2(*(const float2*)&exb[(size_t)qr0 * 48 + v0]);
            exh[mt][ks][1] = pack2(*(const float2*)&exb[(size_t)qr1 * 48 + v0]);
            exh[mt][ks][2] = pack2(*(const float2*)&exb[(size_t)qr0 * 48 + v0 + 8]);
            exh[mt][ks][3] = pack2(*(const float2*)&exb[(size_t)qr1 * 48 + v0 + 8]);
        }
    }
    // per-lane ldmatrix row offsets (bf16 units) within a u-panel [40][56]
    int lrow = lane & 7;
    int lgrp = lane >> 3;                       // 0..3
    int off4 = lrow * 56 + lgrp * 8;            // x4: cols 0..31
    int off2 = lrow * 56 + 32 + (lgrp & 1) * 8; // x2: cols 32..47
    float acc[2][5][4] = {};
    for (int it = 0; it < 6; it++) {
        int cur = it & 1, nxt = cur ^ 1;
        if (it < 5) {
            int uc = (it + 1) * 8;
            for (int j = t; j < 1584; j += 256) {
                int vq = j % 6, dd = (j / 6) % 33, uu = j / 198;
                cpa16(&Wth[nxt * WT_BUF + (uu * 40 + dd) * 56 + vq * 8],
                      wt_g + ((size_t)(uc + uu) * DPW + dd) * 48 + vq * 8);
            }
            CPA_COMMIT;
            CPA_WAIT1;
        } else {
            CPA_WAIT0;
        }
        __syncthreads();
#pragma unroll
        for (int uu = 0; uu < 8; uu++) {
            int u = it * 8 + uu;
            unsigned sa[2][3][4];
#pragma unroll
            for (int mt = 0; mt < 2; mt++) {
                __nv_bfloat162 e0 =
                    __bfloat162bfloat162(Eys[u * 256 + wid * 32 + mt * 16 + g]);
                __nv_bfloat162 e1 =
                    __bfloat162bfloat162(Eys[u * 256 + wid * 32 + mt * 16 + g + 8]);
#pragma unroll
                for (int ks = 0; ks < 3; ks++) {
                    sa[mt][ks][0] = hmul2u(exh[mt][ks][0], e0);
                    sa[mt][ks][1] = hmul2u(exh[mt][ks][1], e1);
                    sa[mt][ks][2] = hmul2u(exh[mt][ks][2], e0);
                    sa[mt][ks][3] = hmul2u(exh[mt][ks][3], e1);
                }
            }
            const __nv_bfloat16* panel = Wth + cur * WT_BUF + uu * 40 * 56;
#pragma unroll
            for (int nt = 0; nt < 5; nt++) {
                unsigned a4 = (unsigned)__cvta_generic_to_shared(panel + nt * 8 * 56 + off4);
                unsigned a2 = (unsigned)__cvta_generic_to_shared(panel + nt * 8 * 56 + off2);
                unsigned b00, b01, b10, b11, b20, b21;
                asm volatile(
                    "ldmatrix.sync.aligned.m8n8.x4.shared.b16 {%0,%1,%2,%3}, [%4];\n"
                    : "=r"(b00), "=r"(b01), "=r"(b10), "=r"(b11)
                    : "r"(a4));
                asm volatile(
                    "ldmatrix.sync.aligned.m8n8.x2.shared.b16 {%0,%1}, [%2];\n"
                    : "=r"(b20), "=r"(b21)
                    : "r"(a2));
#pragma unroll
                for (int mt = 0; mt < 2; mt++) {
                    mma16816(acc[mt][nt], sa[mt][0], b00, b01);
                    mma16816(acc[mt][nt], sa[mt][1], b10, b11);
                    mma16816(acc[mt][nt], sa[mt][2], b20, b21);
                }
            }
        }
        __syncthreads();
    }
    // epilogue: Z = col 32 -> acc[mt][4][0]/[2] at tg==0
    int n = ng >> 3, gh = ng & 7;
    int src = (lane >> 2) << 2;
#pragma unroll
    for (int mt = 0; mt < 2; mt++) {
        int qr0 = qw + mt * 16 + g, qr1 = qr0 + 8;
        float z0 = __shfl_sync(0xffffffffu, acc[mt][4][0], src);
        float z1 = __shfl_sync(0xffffffffu, acc[mt][4][2], src);
        float zi0 = 1.0f / z0, zi1 = 1.0f / z1;
        size_t col0 = (size_t)(n * PP + qr0) * CC;
        size_t col1 = (size_t)(n * PP + qr1) * CC;
#pragma unroll
        for (int nt = 0; nt < 4; nt++) {
            int c = gh * DD + nt * 8 + tg * 2;
            __nv_bfloat162 b0 = __float22bfloat162_rn(
                make_float2(acc[mt][nt][0] * zi0, acc[mt][nt][1] * zi0));
            __nv_bfloat162 b1 = __float22bfloat162_rn(
                make_float2(acc[mt][nt][2] * zi1, acc[mt][nt][3] * zi1));
            *(__nv_bfloat162*)&g_attT[col0 + c] = b0;
            *(__nv_bfloat162*)&g_attT[col1 + c] = b1;
        }
    }
}

// ---------------- bilinear upsample + bias + residual ----------------
__device__ __forceinline__ void taps48(int o, int& i0, int& i1, float& w0, float& w1) {
    int tt = o >> 1;
    if ((o & 1) == 0) {
        if (tt == 0) { i0 = 0; i1 = 0; w0 = 1.f; w1 = 0.f; }
        else { i0 = tt - 1; i1 = tt; w0 = 0.25f; w1 = 0.75f; }
    } else {
        if (tt == 47) { i0 = 47; i1 = 47; w0 = 1.f; w1 = 0.f; }
        else { i0 = tt; i1 = tt + 1; w0 = 0.75f; w1 = 0.25f; }
    }
}

__global__ void k_final(const float* __restrict__ x, const float* __restrict__ bp,
                        const float* __restrict__ gamma, float* __restrict__ out) {
    int i = blockIdx.x * 256 + threadIdx.x;
    int j = i % WW;
    int r = (i / WW) % HH;
    int c = (i / (HH * WW)) % CC;
    int n = i / (CC * HH * WW);
    int r0, r1, c0, c1;
    float rw0, rw1, cw0, cw1;
    taps48(r, r0, r1, rw0, rw1);
    taps48(j, c0, c1, cw0, cw1);
    const float* pr = g_proj + (size_t)c * COLS + n * PP;
    float v00 = pr[r0 * HS + c0], v01 = pr[r0 * HS + c1];
    float v10 = pr[r1 * HS + c0], v11 = pr[r1 * HS + c1];
    float bi = rw0 * (cw0 * v00 + cw1 * v01) + rw1 * (cw0 * v10 + cw1 * v11);
    out[i] = gamma[0] * (bi + bp[c]) + x[i];
}

// ---------------- launch ----------------
extern "C" void kernel_launch(void* const* d_in, const int* in_sizes, int n_in,
                              void* d_out, int out_size) {
    (void)in_sizes; (void)n_in; (void)out_size;
    const float* x = (const float*)d_in[0];
    const float* Wq = (const float*)d_in[1];
    const float* Wk = (const float*)d_in[2];
    const float* Wv = (const float*)d_in[3];
    const float* Wx = (const float*)d_in[4];
    const float* Wy = (const float*)d_in[5];
    const float* ab = (const float*)d_in[6];
    const float* Wp = (const float*)d_in[7];
    const float* bp = (const float*)d_in[8];
    const float* gamma = (const float*)d_in[9];
    float* out = (float*)d_out;

    cudaFuncSetAttribute(k_attn_mma, cudaFuncAttributeMaxDynamicSharedMemorySize,
                         ATT_SMEM);
    cudaFuncSetAttribute(k_gemm_qkv, cudaFuncAttributeMaxDynamicSharedMemorySize,
                         QKV_SMEM);

    k_prep_w<<<384, 256>>>(Wq, Wk, Wv, Wp, Wx, Wy);
    k_subT<<<dim3(COLS / 32, CC / 32), 256>>>(x);
    k_pos2<<<dim3(95, 8), 256>>>();
    k_gemm_qkv<<<dim3(36, 3), 512, QKV_SMEM>>>();
    k_exy<<<16 * HS, 256>>>();
    k_ekf<<<16, 256>>>(ab);
    k_wt8<<<(16 * 48 * DPW * 48) / 2048, 256>>>();
    k_attn_mma<<<dim3(PP / 256, 16), 256, ATT_SMEM>>>();
    k_gemm_wp<<<dim3(36, 2), 256>>>();
    k_final<<<(NN * CC * HH * WW) / 256, 256>>>(x, bp, gamma, out);
}